// round 13
// baseline (speedup 1.0000x reference)
#include <cuda_runtime.h>
#include <cuda_fp16.h>
#include <cstdint>
#include <math.h>

// Problem dims (SimpleLSTM): B=64, T=512, D=1024, H=1024
#define B_  64
#define T_  512
#define D_  1024
#define H_  1024
#define G4_ 4096   // 4*H

// ---------------- scratch (device globals: allocation-free) ----------------
__device__ float g_xproj[(size_t)T_ * B_ * G4_];      // [T*B][4H] fp32 (m = t*64+b)
// xs in fp16 A-frag (m16n8k16) layout: uint4 idx ((strip*64 + ki)*32 + lane)
__device__ __half g_xsA_h[(size_t)2048 * 64 * 32 * 8];   // 64MB
// Wx in fp16 B-frag pair layout: uint4 idx ((ng2*64 + ki)*32 + lane)
__device__ __half g_WxB_h[(size_t)256 * 64 * 32 * 8];    // 8MB
// hidden state in fp16 A-frag layout (verified R10), double buffered
__device__ __half g_hperm_h[2][B_ * H_];

// hierarchical barrier state (counters return to 0 after each use -> replay-safe)
struct PadCnt { unsigned v; unsigned pad[31]; };   // 128B spacing
__device__ PadCnt g_cnt1[8];
__device__ unsigned g_cnt2 = 0;
__device__ unsigned g_bar_gen = 0;

// ---------------- helpers ----------------
__device__ __forceinline__ void cp_async16(void* dst, const void* src) {
    uint32_t s = (uint32_t)__cvta_generic_to_shared(dst);
    asm volatile("cp.async.cg.shared.global [%0], [%1], 16;\n" :: "r"(s), "l"(src));
}
__device__ __forceinline__ void cp_commit() { asm volatile("cp.async.commit_group;\n"); }
template<int N>
__device__ __forceinline__ void cp_wait() { asm volatile("cp.async.wait_group %0;\n" :: "n"(N)); }

// fp16 MMA, fp32 accumulate: A 4 regs (16x16 f16), B 2 regs (16x8 f16)
__device__ __forceinline__ void mma_f16(float4& d, const uint4& a,
                                        unsigned b0, unsigned b1) {
    asm volatile(
        "mma.sync.aligned.m16n8k16.row.col.f32.f16.f16.f32 "
        "{%0,%1,%2,%3}, {%4,%5,%6,%7}, {%8,%9}, {%0,%1,%2,%3};"
        : "+f"(d.x), "+f"(d.y), "+f"(d.z), "+f"(d.w)
        : "r"(a.x), "r"(a.y), "r"(a.z), "r"(a.w), "r"(b0), "r"(b1));
}
__device__ __forceinline__ float sigmoid_f(float x) {
    return __fdividef(1.0f, 1.0f + __expf(-x));
}
__device__ __forceinline__ float tanh_f(float x) {
    return __fdividef(2.0f, 1.0f + __expf(-2.0f * x)) - 1.0f;
}
__device__ __forceinline__ unsigned pack_h2(float lo, float hi) {
    __half2 h2 = __floats2half2_rn(lo, hi);
    return *reinterpret_cast<unsigned*>(&h2);
}

// hierarchical arrive for 64 blocks: 8 groups of 8 + master.
__device__ __forceinline__ void bar_arrive64(int bIdx) {
    __threadfence();                               // release prior global stores
    unsigned o = atomicAdd(&g_cnt1[bIdx >> 3].v, 1u);
    if (o == 7u) {
        unsigned o2 = atomicAdd(&g_cnt2, 1u);
        if (o2 == 7u) {
            #pragma unroll
            for (int i = 0; i < 8; i++) atomicExch(&g_cnt1[i].v, 0u);
            atomicExch(&g_cnt2, 0u);
            __threadfence();
            atomicAdd(&g_bar_gen, 1u);
        }
    }
}

// ============================================================================
// P1: permute xs -> g_xsA_h (fp16 A-frag layout).  (round-12, proven)
// ============================================================================
__global__ void __launch_bounds__(256) permA_kernel(const float* __restrict__ xs) {
    size_t x = (size_t)blockIdx.x * 256 + threadIdx.x;   // < 4,194,304
    int lane  = (int)(x & 31);
    int ki    = (int)((x >> 5) & 63);
    int strip = (int)(x >> 11);
    int r  = strip * 16 + (lane >> 2);
    int k  = ki * 16 + (lane & 3) * 2;
    auto ld2 = [&](int m, int kk) -> unsigned {
        int b = m & 63, t = m >> 6;
        const float* p = xs + ((size_t)b * T_ + t) * D_ + kk;
        return pack_h2(p[0], p[1]);
    };
    uint4 v;
    v.x = ld2(r,     k);
    v.y = ld2(r + 8, k);
    v.z = ld2(r,     k + 8);
    v.w = ld2(r + 8, k + 8);
    reinterpret_cast<uint4*>(g_xsA_h)[x] = v;
}

// ============================================================================
// P2: permute Wx -> g_WxB_h (fp16 B-frag pair layout).  (round-12, proven)
// ============================================================================
__global__ void __launch_bounds__(256) permB_kernel(const float* __restrict__ Wx) {
    size_t y = (size_t)blockIdx.x * 256 + threadIdx.x;   // < 524,288
    int lane = (int)(y & 31);
    int ki   = (int)((y >> 5) & 63);
    int ng2  = (int)(y >> 11);
    int tk = (lane & 3) * 2;
    int n  = lane >> 2;
    int kb = ki * 16;
    unsigned wd[4];
    #pragma unroll
    for (int w = 0; w < 4; w++) {
        int ng   = ng2 * 2 + (w >> 1);
        int krow = kb + tk + 8 * (w & 1);
        const float* colp = Wx + (size_t)ng * 8 + n;
        wd[w] = pack_h2(__ldg(colp + (size_t)krow * G4_),
                        __ldg(colp + (size_t)(krow + 1) * G4_));
    }
    reinterpret_cast<uint4*>(g_WxB_h)[y] = make_uint4(wd[0], wd[1], wd[2], wd[3]);
}

// ============================================================================
// Kernel G: xproj = xsA_h @ WxB_h  (round-12, proven, byte-identical)
// ============================================================================
__global__ void __launch_bounds__(256) xproj_kernel() {
    extern __shared__ uint4 smG[];   // 3 stages x 4096 uint4 = 196,608 B
    const int tid  = threadIdx.x;
    const int lane = tid & 31;
    const int w    = tid >> 5;
    const int wm   = w >> 2;
    const int wn   = w & 3;
    const int mt   = blockIdx.y;
    const int nt   = blockIdx.x;

    const uint4* xsA = reinterpret_cast<const uint4*>(g_xsA_h);
    const uint4* WxB = reinterpret_cast<const uint4*>(g_WxB_h);

    auto issue = [&](int ch) {
        uint4* stA = smG + (ch % 3) * 4096;
        uint4* stB = stA + 2048;
        #pragma unroll
        for (int it = 0; it < 8; it++) {            // A: 2048 uint4
            int lin = tid + it * 256;
            int ln  = lin & 31;
            int dki = (lin >> 5) & 7;
            int st  = lin >> 8;
            cp_async16(&stA[(st * 8 + dki) * 32 + ln],
                       &xsA[((size_t)(mt * 8 + st) * 64 + ch * 8 + dki) * 32 + ln]);
        }
        #pragma unroll
        for (int it = 0; it < 8; it++) {            // B: 2048 uint4
            int lin = tid + it * 256;
            int ln  = lin & 31;
            int dki = (lin >> 5) & 7;
            int lg  = lin >> 8;                     // local ng2 0..7
            cp_async16(&stB[(lg * 8 + dki) * 32 + ln],
                       &WxB[((size_t)(nt * 8 + lg) * 64 + ch * 8 + dki) * 32 + ln]);
        }
    };

    float4 acc[4][4];
    #pragma unroll
    for (int s = 0; s < 4; s++)
        #pragma unroll
        for (int g = 0; g < 4; g++)
            acc[s][g] = make_float4(0.f, 0.f, 0.f, 0.f);

    issue(0); cp_commit();
    issue(1); cp_commit();

    #pragma unroll 1
    for (int ch = 0; ch < 8; ch++) {
        __syncthreads();
        if (ch + 2 < 8) { issue(ch + 2); cp_commit(); }
        if (ch < 6) cp_wait<2>(); else if (ch == 6) cp_wait<1>(); else cp_wait<0>();
        __syncthreads();

        const uint4* stA = smG + (ch % 3) * 4096;
        const uint4* stB = stA + 2048;
        #pragma unroll
        for (int d = 0; d < 8; d++) {
            uint4 a[4];
            #pragma unroll
            for (int s = 0; s < 4; s++)
                a[s] = stA[((wm * 4 + s) * 8 + d) * 32 + lane];
            uint4 w0 = stB[((wn * 2 + 0) * 8 + d) * 32 + lane];
            uint4 w1 = stB[((wn * 2 + 1) * 8 + d) * 32 + lane];
            #pragma unroll
            for (int s = 0; s < 4; s++) {
                mma_f16(acc[s][0], a[s], w0.x, w0.y);
                mma_f16(acc[s][1], a[s], w0.z, w0.w);
                mma_f16(acc[s][2], a[s], w1.x, w1.y);
                mma_f16(acc[s][3], a[s], w1.z, w1.w);
            }
        }
    }

    int r  = lane >> 2;
    int c2 = (lane & 3) * 2;
    #pragma unroll
    for (int s = 0; s < 4; s++)
        #pragma unroll
        for (int g = 0; g < 4; g++) {
            size_t row = (size_t)mt * 128 + (wm * 4 + s) * 16 + r;
            size_t col = (size_t)nt * 128 + (wn * 4 + g) * 8 + c2;
            *reinterpret_cast<float2*>(g_xproj + row * G4_ + col) =
                make_float2(acc[s][g].x, acc[s][g].y);
            *reinterpret_cast<float2*>(g_xproj + (row + 8) * G4_ + col) =
                make_float2(acc[s][g].z, acc[s][g].w);
        }
}

// ============================================================================
// Kernel B: persistent LSTM scan, 64 blocks x 256 threads (8 warps), fp16.
//   Block owns h-cols [bIdx*16, +16) (= hperm ki == bIdx) x full batch.
//   Warp (kq = w&3, mh = w>>2): rows mh*32..+32 x ALL 64 gate-cols over
//   k-quarter kq. Per ki(16): 2 A LDS.128 + 4 B LDS.128 -> 16 MMAs.
//   Warp-local cp.async pipeline (disjoint A slices; no in-loop syncthreads).
//   Broadcast = 64 x 128KB = 8MB/step (halved). sg ALIASES hs (safe: written
//   only after cp_wait<0> + syncthreads; re-written next step only after the
//   grid barrier). Barrier: 64 arrivals (8 groups of 8).
// ============================================================================
__global__ void __launch_bounds__(256, 1) lstm_scan_kernel(
    const float* __restrict__ c0, const float* __restrict__ h0,
    const float* __restrict__ Wh, const float* __restrict__ bias,
    float* __restrict__ out)
{
    extern __shared__ float sm[];
    // Whs: 8192 uint4 = 128KB, [(kq*16+ki2)*4 + p][lane]
    uint4* Whs4 = reinterpret_cast<uint4*>(sm);
    // hs: 4096 uint4 = 64KB at float offset 32768; [warp(8)][stage(4)][128]
    uint4* hs4  = reinterpret_cast<uint4*>(sm) + 8192;
    // sg: 16896 floats, ALIASES hs ([kq(4)][row(64) stride 66])
    float* sg   = sm + 32768;

    const int tid  = threadIdx.x;
    const int lane = tid & 31;
    const int w    = tid >> 5;
    const int kq   = w & 3;             // k-quarter (256 k)
    const int mh   = w >> 2;            // row half (32 rows)
    const int bIdx = blockIdx.x;        // 0..63
    const int j0   = bIdx * 16;

    // ---- build Whs (fp16 B-frag pairs, 64 gate-cols):
    //   col c = (p*2 + (w>>1))*8 + (lane>>2); gate = c>>4, hcol = c&15
    //   k = kq*256 + ki2*16 + (lane&3)*2 + 8*(w&1) (+1 for hi half)
    for (int i = tid; i < 8192; i += 256) {
        int ln  = i & 31;
        int p   = (i >> 5) & 3;
        int ki2 = (i >> 7) & 15;
        int kqq = i >> 11;
        int tk = (ln & 3) * 2;
        int nn = ln >> 2;
        int kb = kqq * 256 + ki2 * 16;
        unsigned wd[4];
        #pragma unroll
        for (int ww = 0; ww < 4; ww++) {
            int c    = (p * 2 + (ww >> 1)) * 8 + nn;   // 0..63
            int gate = c >> 4, hcol = c & 15;
            int krow = kb + tk + 8 * (ww & 1);
            const float* colp = Wh + (size_t)gate * H_ + j0 + hcol;
            wd[ww] = pack_h2(__ldg(colp + (size_t)krow * G4_),
                             __ldg(colp + (size_t)(krow + 1) * G4_));
        }
        Whs4[i] = make_uint4(wd[0], wd[1], wd[2], wd[3]);
    }

    // ---- per-thread ownership: j = j0 + (tid&15), rows b_q = (tid>>4) + 16q
    const int rbase = tid >> 4;          // 0..15
    const int jj    = tid & 15;
    const int j     = j0 + jj;
    int bq[4];
    #pragma unroll
    for (int q = 0; q < 4; q++) bq[q] = rbase + q * 16;

    float creg[4], bia[4];
    #pragma unroll
    for (int g = 0; g < 4; g++) bia[g] = __ldg(bias + g * H_ + j);
    #pragma unroll
    for (int q = 0; q < 4; q++) creg[q] = __ldg(c0 + (size_t)bq[q] * H_ + j);

    // ---- h write coords (fp16 A-frag; ki == bIdx, strip == q)
    const int lane_w = (rbase & 7) * 4 + ((jj & 7) >> 1);
    const int v_w    = ((jj >> 3) << 1) | (rbase >> 3);
    const int hi_w   = jj & 1;

    // ---- init g_hperm_h[0] = fp16(h0)
    #pragma unroll
    for (int q = 0; q < 4; q++) {
        size_t hidx = ((((size_t)bIdx * 4 + q) * 32 + lane_w) * 4 + v_w) * 2 + hi_w;
        g_hperm_h[0][hidx] = __float2half_rn(__ldg(h0 + (size_t)bq[q] * H_ + j));
    }

    // ---- xproj prefetch
    float xpr[4][4];
    auto prefetch_xp = [&](int t) {
        const float* xp = g_xproj + (size_t)t * B_ * G4_;
        #pragma unroll
        for (int q = 0; q < 4; q++)
            #pragma unroll
            for (int g = 0; g < 4; g++)
                xpr[q][g] = __ldg(xp + (size_t)bq[q] * G4_ + g * H_ + j);
    };
    prefetch_xp(0);

    // ---- initial global grid sync
    __syncthreads();
    {
        unsigned mygen = 0;
        if (tid == 0) {
            volatile unsigned* genp = &g_bar_gen;
            mygen = *genp;
            bar_arrive64(bIdx);
            while (*genp == mygen) { }
            __threadfence();
        }
        __syncthreads();
    }

    const int warp_base = (kq * 2 + mh) * 512;   // uint4 offset in hs4

    for (int t = 0; t < T_; t++) {
        const uint4* hc4 = reinterpret_cast<const uint4*>(g_hperm_h[t & 1]);
        __half* hnext    = g_hperm_h[(t + 1) & 1];

        // warp-local issue of chunk ci (2 ki, 2 strips of this warp): 128 uint4
        auto issue = [&](int ci) {
            uint4* dst = hs4 + warp_base + (ci & 3) * 128;
            #pragma unroll
            for (int it = 0; it < 4; it++) {
                int dki   = it >> 1;
                int s     = it & 1;
                int strip = mh * 2 + s;
                int ki    = kq * 16 + ci * 2 + dki;
                cp_async16(&dst[(dki * 2 + s) * 32 + lane],
                           &hc4[((size_t)ki * 4 + strip) * 32 + lane]);
            }
        };

        issue(0); cp_commit();
        issue(1); cp_commit();
        issue(2); cp_commit();
        issue(3); cp_commit();

        float4 acc[2][8];   // [strip-local][octet]
        #pragma unroll
        for (int s = 0; s < 2; s++)
            #pragma unroll
            for (int o = 0; o < 8; o++)
                acc[s][o] = make_float4(0.f, 0.f, 0.f, 0.f);

        #pragma unroll 4
        for (int ch = 0; ch < 8; ch++) {
            if (ch < 5)       cp_wait<3>();
            else if (ch == 5) cp_wait<2>();
            else if (ch == 6) cp_wait<1>();
            else              cp_wait<0>();

            const uint4* st = hs4 + warp_base + (ch & 3) * 128;
            #pragma unroll
            for (int d = 0; d < 2; d++) {
                int ki2 = ch * 2 + d;
                uint4 a0 = st[(d * 2 + 0) * 32 + lane];
                uint4 a1 = st[(d * 2 + 1) * 32 + lane];
                #pragma unroll
                for (int p = 0; p < 4; p++) {
                    uint4 wv = Whs4[((kq * 16 + ki2) * 4 + p) * 32 + lane];
                    mma_f16(acc[0][2 * p],     a0, wv.x, wv.y);
                    mma_f16(acc[0][2 * p + 1], a0, wv.z, wv.w);
                    mma_f16(acc[1][2 * p],     a1, wv.x, wv.y);
                    mma_f16(acc[1][2 * p + 1], a1, wv.z, wv.w);
                }
            }
            if (ch + 4 < 8) { issue(ch + 4); cp_commit(); }
        }

        // all cp.async complete (cp_wait<0> at ch=7) and all warps done
        // reading hs before sg overwrites it (aliased region):
        __syncthreads();

        // ---- stage partials: sg[kq][row (stride 66)][col = octet*8 + c2]
        {
            int r  = lane >> 2;
            int c2 = (lane & 3) * 2;
            float* base = sg + (size_t)kq * 64 * 66;
            #pragma unroll
            for (int s = 0; s < 2; s++)
                #pragma unroll
                for (int o = 0; o < 8; o++) {
                    int row0 = (mh * 2 + s) * 16 + r;
                    *reinterpret_cast<float2*>(base + row0 * 66 + o * 8 + c2) =
                        make_float2(acc[s][o].x, acc[s][o].y);
                    *reinterpret_cast<float2*>(base + (row0 + 8) * 66 + o * 8 + c2) =
                        make_float2(acc[s][o].z, acc[s][o].w);
                }
        }
        __syncthreads();

        // ---- reduce 4 k-quarters + fused elementwise (flax order i,f,g,o)
        float hnv[4];
        #pragma unroll
        for (int q = 0; q < 4; q++) {
            float gv[4];
            #pragma unroll
            for (int g = 0; g < 4; g++) {
                float sum = 0.f;
                #pragma unroll
                for (int kk = 0; kk < 4; kk++)
                    sum += sg[(size_t)kk * 64 * 66 + bq[q] * 66 + g * 16 + jj];
                gv[g] = sum;
            }
            float pi = gv[0] + xpr[q][0] + bia[0];
            float pf = gv[1] + xpr[q][1] + bia[1];
            float pg = gv[2] + xpr[q][2] + bia[2];
            float po = gv[3] + xpr[q][3] + bia[3];
            float cn = sigmoid_f(pf) * creg[q] + sigmoid_f(pi) * tanh_f(pg);
            float hn = sigmoid_f(po) * tanh_f(cn);
            creg[q] = cn;
            hnv[q] = hn;
        }

        // ---- write hnext (fp16, permuted; ki = bIdx, strip = q)
        #pragma unroll
        for (int q = 0; q < 4; q++) {
            size_t hidx = ((((size_t)bIdx * 4 + q) * 32 + lane_w) * 4 + v_w) * 2 + hi_w;
            hnext[hidx] = __float2half_rn(hnv[q]);
        }

        // ---- barrier arrive (hierarchical; releases h stores + guards sg alias)
        __syncthreads();
        unsigned mygen = 0;
        if (tid == 0) {
            volatile unsigned* genp = &g_bar_gen;
            mygen = *genp;
            bar_arrive64(bIdx);
        }

        // ---- hidden work between arrive and wait: ys stores + next prefetch
        #pragma unroll
        for (int q = 0; q < 4; q++)
            out[2 * B_ * H_ + ((size_t)bq[q] * T_ + t) * H_ + j] = hnv[q];
        if (t == T_ - 1) {
            #pragma unroll
            for (int q = 0; q < 4; q++)
                out[B_ * H_ + (size_t)bq[q] * H_ + j] = hnv[q];
        }
        if (t + 1 < T_) prefetch_xp(t + 1);

        // ---- barrier wait
        if (tid == 0) {
            volatile unsigned* genp = &g_bar_gen;
            while (*genp == mygen) { }
            __threadfence();                    // acquire
        }
        __syncthreads();
    }

    // cT
    #pragma unroll
    for (int q = 0; q < 4; q++)
        out[(size_t)bq[q] * H_ + j] = creg[q];
}

// ============================================================================
// Launch. Inputs: c0, h0, xs, Wx, Wh, b. Output fp32: [cT][hT][ys]
// ============================================================================
extern "C" void kernel_launch(void* const* d_in, const int* in_sizes, int n_in,
                              void* d_out, int out_size) {
    const float* c0   = (const float*)d_in[0];
    const float* h0   = (const float*)d_in[1];
    const float* xs   = (const float*)d_in[2];
    const float* Wx   = (const float*)d_in[3];
    const float* Wh   = (const float*)d_in[4];
    const float* bias = (const float*)d_in[5];
    float* out = (float*)d_out;

    constexpr int G_SMEM    = 3 * 4096 * 16;                 // 196,608 B
    constexpr int SCAN_SMEM = (32768 + 16896) * 4;           // 198,656 B
    cudaFuncSetAttribute(xproj_kernel,
                         cudaFuncAttributeMaxDynamicSharedMemorySize, G_SMEM);
    cudaFuncSetAttribute(lstm_scan_kernel,
                         cudaFuncAttributeMaxDynamicSharedMemorySize, SCAN_SMEM);

    permA_kernel<<<16384, 256>>>(xs);     // 4,194,304 uint4 / 256
    permB_kernel<<<2048, 256>>>(Wx);      // 524,288 uint4 / 256
    dim3 gridG(32, 256);
    xproj_kernel<<<gridG, 256, G_SMEM>>>();
    lstm_scan_kernel<<<64, 256, SCAN_SMEM>>>(c0, h0, Wh, bias, out);
}

// round 14
// speedup vs baseline: 1.1584x; 1.1584x over previous
#include <cuda_runtime.h>
#include <cuda_fp16.h>
#include <cstdint>
#include <math.h>

// Problem dims (SimpleLSTM): B=64, T=512, D=1024, H=1024
#define B_  64
#define T_  512
#define D_  1024
#define H_  1024
#define G4_ 4096   // 4*H

// ---------------- scratch (device globals: allocation-free) ----------------
__device__ float g_xproj[(size_t)T_ * B_ * G4_];      // [T*B][4H] fp32 (m = t*64+b)
// xs in fp16 A-frag (m16n8k16) layout: uint4 idx ((strip*64 + ki)*32 + lane)
__device__ __half g_xsA_h[(size_t)2048 * 64 * 32 * 8];   // 64MB
// Wx in fp16 B-frag pair layout: uint4 idx ((ng2*64 + ki)*32 + lane)
__device__ __half g_WxB_h[(size_t)256 * 64 * 32 * 8];    // 8MB
// hidden state in fp16 A-frag layout (verified R10), double buffered
__device__ __half g_hperm_h[2][B_ * H_];

// hierarchical barrier state (counters return to 0 after each use -> replay-safe)
struct PadCnt { unsigned v; unsigned pad[31]; };   // 128B spacing
__device__ PadCnt g_cnt1[8];
__device__ unsigned g_cnt2 = 0;
__device__ unsigned g_bar_gen = 0;

// ---------------- helpers ----------------
__device__ __forceinline__ void cp_async16(void* dst, const void* src) {
    uint32_t s = (uint32_t)__cvta_generic_to_shared(dst);
    asm volatile("cp.async.cg.shared.global [%0], [%1], 16;\n" :: "r"(s), "l"(src));
}
__device__ __forceinline__ void cp_commit() { asm volatile("cp.async.commit_group;\n"); }
template<int N>
__device__ __forceinline__ void cp_wait() { asm volatile("cp.async.wait_group %0;\n" :: "n"(N)); }

// fp16 MMA, fp32 accumulate: A 4 regs (16x16 f16), B 2 regs (16x8 f16)
__device__ __forceinline__ void mma_f16(float4& d, const uint4& a,
                                        unsigned b0, unsigned b1) {
    asm volatile(
        "mma.sync.aligned.m16n8k16.row.col.f32.f16.f16.f32 "
        "{%0,%1,%2,%3}, {%4,%5,%6,%7}, {%8,%9}, {%0,%1,%2,%3};"
        : "+f"(d.x), "+f"(d.y), "+f"(d.z), "+f"(d.w)
        : "r"(a.x), "r"(a.y), "r"(a.z), "r"(a.w), "r"(b0), "r"(b1));
}
__device__ __forceinline__ float sigmoid_f(float x) {
    return __fdividef(1.0f, 1.0f + __expf(-x));
}
__device__ __forceinline__ float tanh_f(float x) {
    return __fdividef(2.0f, 1.0f + __expf(-2.0f * x)) - 1.0f;
}
__device__ __forceinline__ unsigned pack_h2(float lo, float hi) {
    __half2 h2 = __floats2half2_rn(lo, hi);
    return *reinterpret_cast<unsigned*>(&h2);
}

// hierarchical arrive: ~24 serialized atomic slots instead of 128.
__device__ __forceinline__ void bar_arrive(int bIdx) {
    __threadfence();                               // release prior global stores
    unsigned o = atomicAdd(&g_cnt1[bIdx >> 4].v, 1u);
    if (o == 15u) {
        unsigned o2 = atomicAdd(&g_cnt2, 1u);
        if (o2 == 7u) {
            #pragma unroll
            for (int i = 0; i < 8; i++) atomicExch(&g_cnt1[i].v, 0u);
            atomicExch(&g_cnt2, 0u);
            __threadfence();
            atomicAdd(&g_bar_gen, 1u);
        }
    }
}

// ============================================================================
// P1: permute xs -> g_xsA_h (fp16 A-frag layout).  (round-12, proven)
// ============================================================================
__global__ void __launch_bounds__(256) permA_kernel(const float* __restrict__ xs) {
    size_t x = (size_t)blockIdx.x * 256 + threadIdx.x;   // < 4,194,304
    int lane  = (int)(x & 31);
    int ki    = (int)((x >> 5) & 63);
    int strip = (int)(x >> 11);
    int r  = strip * 16 + (lane >> 2);
    int k  = ki * 16 + (lane & 3) * 2;
    auto ld2 = [&](int m, int kk) -> unsigned {
        int b = m & 63, t = m >> 6;
        const float* p = xs + ((size_t)b * T_ + t) * D_ + kk;
        return pack_h2(p[0], p[1]);
    };
    uint4 v;
    v.x = ld2(r,     k);
    v.y = ld2(r + 8, k);
    v.z = ld2(r,     k + 8);
    v.w = ld2(r + 8, k + 8);
    reinterpret_cast<uint4*>(g_xsA_h)[x] = v;
}

// ============================================================================
// P2: permute Wx -> g_WxB_h (fp16 B-frag pair layout).  (round-12, proven)
// ============================================================================
__global__ void __launch_bounds__(256) permB_kernel(const float* __restrict__ Wx) {
    size_t y = (size_t)blockIdx.x * 256 + threadIdx.x;   // < 524,288
    int lane = (int)(y & 31);
    int ki   = (int)((y >> 5) & 63);
    int ng2  = (int)(y >> 11);
    int tk = (lane & 3) * 2;
    int n  = lane >> 2;
    int kb = ki * 16;
    unsigned wd[4];
    #pragma unroll
    for (int w = 0; w < 4; w++) {
        int ng   = ng2 * 2 + (w >> 1);
        int krow = kb + tk + 8 * (w & 1);
        const float* colp = Wx + (size_t)ng * 8 + n;
        wd[w] = pack_h2(__ldg(colp + (size_t)krow * G4_),
                        __ldg(colp + (size_t)(krow + 1) * G4_));
    }
    reinterpret_cast<uint4*>(g_WxB_h)[y] = make_uint4(wd[0], wd[1], wd[2], wd[3]);
}

// ============================================================================
// Kernel G: xproj = xsA_h @ WxB_h  (M=32768, N=4096, K=1024), fp16 m16n8k16.
// BM=256, BN=128 block tile (B L2 traffic halved vs 128x128 -> 3GB total).
// 256 thr, 8 warps (wm = w>>1 in 0..3, wn = w&1 in 0..1), warp tile m64 x n64.
// 16 k-chunks of 4 ki(16), 3-stage cp.async.
// Stage: A 2048 uint4 (16 strips x 4 ki x 32) + B 1024 uint4 (8 ng2 x 4 ki x 32)
// ============================================================================
__global__ void __launch_bounds__(256) xproj_kernel() {
    extern __shared__ uint4 smG[];   // 3 stages x 3072 uint4 = 147,456 B
    const int tid  = threadIdx.x;
    const int lane = tid & 31;
    const int w    = tid >> 5;
    const int wm   = w >> 1;    // 0..3 (64-row strip of 256)
    const int wn   = w & 1;     // 0..1 (64-col strip of 128)
    const int mt   = blockIdx.y;       // 0..127
    const int nt   = blockIdx.x;       // 0..31

    const uint4* xsA = reinterpret_cast<const uint4*>(g_xsA_h);
    const uint4* WxB = reinterpret_cast<const uint4*>(g_WxB_h);

    auto issue = [&](int ch) {
        uint4* stA = smG + (ch % 3) * 3072;
        uint4* stB = stA + 2048;
        #pragma unroll
        for (int it = 0; it < 8; it++) {            // A: 2048 uint4
            int lin = tid + it * 256;
            int ln  = lin & 31;
            int dki = (lin >> 5) & 3;
            int st  = lin >> 7;                     // 0..15
            cp_async16(&stA[(st * 4 + dki) * 32 + ln],
                       &xsA[((size_t)(mt * 16 + st) * 64 + ch * 4 + dki) * 32 + ln]);
        }
        #pragma unroll
        for (int it = 0; it < 4; it++) {            // B: 1024 uint4
            int lin = tid + it * 256;
            int ln  = lin & 31;
            int dki = (lin >> 5) & 3;
            int lg  = lin >> 7;                     // local ng2 0..7
            cp_async16(&stB[(lg * 4 + dki) * 32 + ln],
                       &WxB[((size_t)(nt * 8 + lg) * 64 + ch * 4 + dki) * 32 + ln]);
        }
    };

    float4 acc[4][8];   // [strip][octet within warp n64]
    #pragma unroll
    for (int s = 0; s < 4; s++)
        #pragma unroll
        for (int o = 0; o < 8; o++)
            acc[s][o] = make_float4(0.f, 0.f, 0.f, 0.f);

    issue(0); cp_commit();
    issue(1); cp_commit();

    #pragma unroll 1
    for (int ch = 0; ch < 16; ch++) {
        __syncthreads();                       // readers of recycled stage done
        if (ch + 2 < 16) { issue(ch + 2); cp_commit(); }
        if (ch < 14) cp_wait<2>(); else if (ch == 14) cp_wait<1>(); else cp_wait<0>();
        __syncthreads();

        const uint4* stA = smG + (ch % 3) * 3072;
        const uint4* stB = stA + 2048;
        #pragma unroll
        for (int d = 0; d < 4; d++) {
            uint4 a[4];
            #pragma unroll
            for (int s = 0; s < 4; s++)
                a[s] = stA[((wm * 4 + s) * 4 + d) * 32 + lane];
            #pragma unroll
            for (int p = 0; p < 4; p++) {
                uint4 wv = stB[((wn * 4 + p) * 4 + d) * 32 + lane];
                #pragma unroll
                for (int s = 0; s < 4; s++) {
                    mma_f16(acc[s][2 * p],     a[s], wv.x, wv.y);
                    mma_f16(acc[s][2 * p + 1], a[s], wv.z, wv.w);
                }
            }
        }
    }

    // epilogue: fp32 rows to g_xproj. acc[s][o]: rows mt*256+(wm*4+s)*16+r(+8),
    // cols nt*128 + (wn*8+o)*8 + c2(..+1)
    int r  = lane >> 2;
    int c2 = (lane & 3) * 2;
    #pragma unroll
    for (int s = 0; s < 4; s++)
        #pragma unroll
        for (int o = 0; o < 8; o++) {
            size_t row = (size_t)mt * 256 + (wm * 4 + s) * 16 + r;
            size_t col = (size_t)nt * 128 + (wn * 8 + o) * 8 + c2;
            *reinterpret_cast<float2*>(g_xproj + row * G4_ + col) =
                make_float2(acc[s][o].x, acc[s][o].y);
            *reinterpret_cast<float2*>(g_xproj + (row + 8) * G4_ + col) =
                make_float2(acc[s][o].z, acc[s][o].w);
        }
}

// ============================================================================
// Kernel B: persistent LSTM scan (round-12 version, PASSING, byte-identical).
// 128 blocks x 128 thr (4 warps), fp16 m16n8k16, warp-local cp.async pipeline,
// sg reduce, hierarchical barrier.
// ============================================================================
__global__ void __launch_bounds__(128, 1) lstm_scan_kernel(
    const float* __restrict__ c0, const float* __restrict__ h0,
    const float* __restrict__ Wh, const float* __restrict__ bias,
    float* __restrict__ out)
{
    extern __shared__ float sm[];
    uint4* Whs4 = reinterpret_cast<uint4*>(sm);            // 4096 uint4 = 64KB
    uint4* hs4  = reinterpret_cast<uint4*>(sm + 16384);    // 4096 uint4 = 64KB
    float* sg   = sm + 32768;                              // 8704 floats

    const int tid  = threadIdx.x;
    const int lane = tid & 31;
    const int kq   = tid >> 5;          // warp id == k-quarter (256 k each)
    const int bIdx = blockIdx.x;
    const int j0   = bIdx * 8;

    // ---- build Whs (fp16 B-frag, gate-grouped)
    for (int i = tid; i < 4096; i += 128) {
        int ln  = i & 31;
        int p   = (i >> 5) & 1;
        int ki2 = (i >> 6) & 15;
        int kqq = i >> 10;
        int tk = (ln & 3) * 2;
        int n  = ln >> 2;
        int kb = kqq * 256 + ki2 * 16;
        unsigned wd[4];
        #pragma unroll
        for (int w = 0; w < 4; w++) {
            int gidx = 2 * p + (w >> 1);
            int krow = kb + tk + 8 * (w & 1);
            const float* colp = Wh + (size_t)gidx * H_ + j0 + n;
            wd[w] = pack_h2(__ldg(colp + (size_t)krow * G4_),
                            __ldg(colp + (size_t)(krow + 1) * G4_));
        }
        Whs4[i] = make_uint4(wd[0], wd[1], wd[2], wd[3]);
    }

    // ---- per-thread ownership: column j = j0 + (tid&7), rows b_q = rbase+16q
    const int rbase = tid >> 3;
    const int jj    = tid & 7;
    const int j     = j0 + jj;
    int bq[4];
    #pragma unroll
    for (int q = 0; q < 4; q++) bq[q] = rbase + q * 16;

    float creg[4], bia[4];
    #pragma unroll
    for (int g = 0; g < 4; g++) bia[g] = __ldg(bias + g * H_ + j);
    #pragma unroll
    for (int q = 0; q < 4; q++) creg[q] = __ldg(c0 + (size_t)bq[q] * H_ + j);

    // ---- h write coords (fp16 layout)
    const int ki_w   = bIdx >> 1;
    const int lane_w = (rbase & 7) * 4 + (jj >> 1);
    const int v_w    = ((bIdx & 1) << 1) + (rbase >> 3);
    const int hi_w   = jj & 1;

    // ---- init g_hperm_h[0] = fp16(h0)
    #pragma unroll
    for (int q = 0; q < 4; q++) {
        size_t hidx = ((((size_t)ki_w * 4 + q) * 32 + lane_w) * 4 + v_w) * 2 + hi_w;
        g_hperm_h[0][hidx] = __float2half_rn(__ldg(h0 + (size_t)bq[q] * H_ + j));
    }

    // ---- xproj prefetch
    float xpr[4][4];
    auto prefetch_xp = [&](int t) {
        const float* xp = g_xproj + (size_t)t * B_ * G4_;
        #pragma unroll
        for (int q = 0; q < 4; q++)
            #pragma unroll
            for (int g = 0; g < 4; g++)
                xpr[q][g] = __ldg(xp + (size_t)bq[q] * G4_ + g * H_ + j);
    };
    prefetch_xp(0);

    // ---- initial global grid sync
    __syncthreads();
    {
        unsigned mygen = 0;
        if (tid == 0) {
            volatile unsigned* genp = &g_bar_gen;
            mygen = *genp;
            bar_arrive(bIdx);
            while (*genp == mygen) { }
            __threadfence();
        }
        __syncthreads();
    }

    for (int t = 0; t < T_; t++) {
        const uint4* hc4 = reinterpret_cast<const uint4*>(g_hperm_h[t & 1]);
        __half* hnext    = g_hperm_h[(t + 1) & 1];

        auto issue = [&](int ci) {
            uint4* dst = hs4 + kq * 1024 + (ci & 3) * 256;
            #pragma unroll
            for (int it = 0; it < 8; it++) {
                int dki   = it >> 2;
                int strip = it & 3;
                int ki    = kq * 16 + ci * 2 + dki;
                cp_async16(&dst[(dki * 4 + strip) * 32 + lane],
                           &hc4[((size_t)ki * 4 + strip) * 32 + lane]);
            }
        };

        issue(0); cp_commit();
        issue(1); cp_commit();
        issue(2); cp_commit();
        issue(3); cp_commit();

        float4 acc[4][4];   // [strip][gate]
        #pragma unroll
        for (int s = 0; s < 4; s++)
            #pragma unroll
            for (int g = 0; g < 4; g++)
                acc[s][g] = make_float4(0.f, 0.f, 0.f, 0.f);

        #pragma unroll 4
        for (int ch = 0; ch < 8; ch++) {
            if (ch < 5)       cp_wait<3>();
            else if (ch == 5) cp_wait<2>();
            else if (ch == 6) cp_wait<1>();
            else              cp_wait<0>();

            const uint4* st = hs4 + kq * 1024 + (ch & 3) * 256;
            #pragma unroll
            for (int d = 0; d < 2; d++) {
                int ki2 = ch * 2 + d;
                uint4 a[4];
                #pragma unroll
                for (int s = 0; s < 4; s++)
                    a[s] = st[(d * 4 + s) * 32 + lane];
                uint4 w0 = Whs4[((kq * 16 + ki2) * 2 + 0) * 32 + lane];
                uint4 w1 = Whs4[((kq * 16 + ki2) * 2 + 1) * 32 + lane];
                #pragma unroll
                for (int s = 0; s < 4; s++) {
                    mma_f16(acc[s][0], a[s], w0.x, w0.y);
                    mma_f16(acc[s][1], a[s], w0.z, w0.w);
                    mma_f16(acc[s][2], a[s], w1.x, w1.y);
                    mma_f16(acc[s][3], a[s], w1.z, w1.w);
                }
            }
            if (ch + 4 < 8) { issue(ch + 4); cp_commit(); }
        }

        // ---- stage partials: sg[kq][row (stride 34)][col = gate*8 + jj]
        {
            int r  = lane >> 2;
            int c2 = (lane & 3) * 2;
            float* base = sg + (size_t)kq * 64 * 34;
            #pragma unroll
            for (int s = 0; s < 4; s++)
                #pragma unroll
                for (int g = 0; g < 4; g++) {
                    *reinterpret_cast<float2*>(base + (s * 16 + r) * 34 + g * 8 + c2) =
                        make_float2(acc[s][g].x, acc[s][g].y);
                    *reinterpret_cast<float2*>(base + (s * 16 + r + 8) * 34 + g * 8 + c2) =
                        make_float2(acc[s][g].z, acc[s][g].w);
                }
        }
        __syncthreads();

        // ---- reduce 4 k-quarters + fused elementwise (flax order i,f,g,o)
        float hnv[4];
        #pragma unroll
        for (int q = 0; q < 4; q++) {
            float gv[4];
            #pragma unroll
            for (int g = 0; g < 4; g++) {
                float sum = 0.f;
                #pragma unroll
                for (int kk = 0; kk < 4; kk++)
                    sum += sg[((size_t)kk * 64 + bq[q]) * 34 + g * 8 + jj];
                gv[g] = sum;
            }
            float pi = gv[0] + xpr[q][0] + bia[0];
            float pf = gv[1] + xpr[q][1] + bia[1];
            float pg = gv[2] + xpr[q][2] + bia[2];
            float po = gv[3] + xpr[q][3] + bia[3];
            float cn = sigmoid_f(pf) * creg[q] + sigmoid_f(pi) * tanh_f(pg);
            float hn = sigmoid_f(po) * tanh_f(cn);
            creg[q] = cn;
            hnv[q] = hn;
        }

        // ---- write hnext (fp16, permuted)
        #pragma unroll
        for (int q = 0; q < 4; q++) {
            size_t hidx = ((((size_t)ki_w * 4 + q) * 32 + lane_w) * 4 + v_w) * 2 + hi_w;
            hnext[hidx] = __float2half_rn(hnv[q]);
        }

        // ---- barrier arrive (hierarchical; releases h stores)
        __syncthreads();
        unsigned mygen = 0;
        if (tid == 0) {
            volatile unsigned* genp = &g_bar_gen;
            mygen = *genp;
            bar_arrive(bIdx);
        }

        // ---- hidden work between arrive and wait: ys stores + next prefetch
        #pragma unroll
        for (int q = 0; q < 4; q++)
            out[2 * B_ * H_ + ((size_t)bq[q] * T_ + t) * H_ + j] = hnv[q];
        if (t == T_ - 1) {
            #pragma unroll
            for (int q = 0; q < 4; q++)
                out[B_ * H_ + (size_t)bq[q] * H_ + j] = hnv[q];
        }
        if (t + 1 < T_) prefetch_xp(t + 1);

        // ---- barrier wait
        if (tid == 0) {
            volatile unsigned* genp = &g_bar_gen;
            while (*genp == mygen) { }
            __threadfence();                    // acquire
        }
        __syncthreads();
    }

    // cT
    #pragma unroll
    for (int q = 0; q < 4; q++)
        out[(size_t)bq[q] * H_ + j] = creg[q];
}

// ============================================================================
// Launch. Inputs: c0, h0, xs, Wx, Wh, b. Output fp32: [cT][hT][ys]
// ============================================================================
extern "C" void kernel_launch(void* const* d_in, const int* in_sizes, int n_in,
                              void* d_out, int out_size) {
    const float* c0   = (const float*)d_in[0];
    const float* h0   = (const float*)d_in[1];
    const float* xs   = (const float*)d_in[2];
    const float* Wx   = (const float*)d_in[3];
    const float* Wh   = (const float*)d_in[4];
    const float* bias = (const float*)d_in[5];
    float* out = (float*)d_out;

    constexpr int G_SMEM    = 3 * 3072 * 16;                 // 147,456 B
    constexpr int SCAN_SMEM = (16384 + 16384 + 8704) * 4;    // 165,888 B
    cudaFuncSetAttribute(xproj_kernel,
                         cudaFuncAttributeMaxDynamicSharedMemorySize, G_SMEM);
    cudaFuncSetAttribute(lstm_scan_kernel,
                         cudaFuncAttributeMaxDynamicSharedMemorySize, SCAN_SMEM);

    permA_kernel<<<16384, 256>>>(xs);     // 4,194,304 uint4 / 256
    permB_kernel<<<2048, 256>>>(Wx);      // 524,288 uint4 / 256
    dim3 gridG(32, 128);                  // nt x mt (BM=256)
    xproj_kernel<<<gridG, 256, G_SMEM>>>();
    lstm_scan_kernel<<<128, 128, SCAN_SMEM>>>(c0, h0, Wh, bias, out);
}

// round 15
// speedup vs baseline: 1.2672x; 1.0939x over previous
#include <cuda_runtime.h>
#include <cuda_fp16.h>
#include <cstdint>
#include <math.h>

// Problem dims (SimpleLSTM): B=64, T=512, D=1024, H=1024
#define B_  64
#define T_  512
#define D_  1024
#define H_  1024
#define G4_ 4096   // 4*H

// ---------------- scratch (device globals: allocation-free) ----------------
__device__ float g_xproj[(size_t)T_ * B_ * G4_];      // [T*B][4H] fp32 (m = t*64+b)
// xs in fp16 A-frag (m16n8k16) layout: uint4 idx ((strip*64 + ki)*32 + lane)
__device__ __half g_xsA_h[(size_t)2048 * 64 * 32 * 8];   // 64MB
// Wx in fp16 B-frag pair layout: uint4 idx ((ng2*64 + ki)*32 + lane)
__device__ __half g_WxB_h[(size_t)256 * 64 * 32 * 8];    // 8MB
// hidden state fp16 A-frag: uint4 idx ((ki*4 + strip)*32 + lane); ki 0..63,
// strip = row>>4. halves: v0={h[r][k],h[r][k+1]} v1=r+8 v2=k+8 v3=r+8,k+8,
// r = strip*16 + (lane>>2), k = ki*16 + (lane&3)*2. Double buffered.
__device__ __half g_hperm_h[2][B_ * H_];

// per-group barrier state (2 groups x 4 subgroups of 16; reset to 0 each use)
struct PadCnt { unsigned v; unsigned pad[31]; };   // 128B spacing
__device__ PadCnt g_cnt1[8];     // [g*4 + sub]
__device__ PadCnt g_cnt2g[2];
__device__ PadCnt g_geng[2];

// ---------------- helpers ----------------
__device__ __forceinline__ void cp_async16(void* dst, const void* src) {
    uint32_t s = (uint32_t)__cvta_generic_to_shared(dst);
    asm volatile("cp.async.cg.shared.global [%0], [%1], 16;\n" :: "r"(s), "l"(src));
}
__device__ __forceinline__ void cp_commit() { asm volatile("cp.async.commit_group;\n"); }
template<int N>
__device__ __forceinline__ void cp_wait() { asm volatile("cp.async.wait_group %0;\n" :: "n"(N)); }

// fp16 MMA, fp32 accumulate: A 4 regs (16x16 f16), B 2 regs (16x8 f16)
__device__ __forceinline__ void mma_f16(float4& d, const uint4& a,
                                        unsigned b0, unsigned b1) {
    asm volatile(
        "mma.sync.aligned.m16n8k16.row.col.f32.f16.f16.f32 "
        "{%0,%1,%2,%3}, {%4,%5,%6,%7}, {%8,%9}, {%0,%1,%2,%3};"
        : "+f"(d.x), "+f"(d.y), "+f"(d.z), "+f"(d.w)
        : "r"(a.x), "r"(a.y), "r"(a.z), "r"(a.w), "r"(b0), "r"(b1));
}
__device__ __forceinline__ float sigmoid_f(float x) {
    return __fdividef(1.0f, 1.0f + __expf(-x));
}
__device__ __forceinline__ float tanh_f(float x) {
    return __fdividef(2.0f, 1.0f + __expf(-2.0f * x)) - 1.0f;
}
__device__ __forceinline__ unsigned pack_h2(float lo, float hi) {
    __half2 h2 = __floats2half2_rn(lo, hi);
    return *reinterpret_cast<unsigned*>(&h2);
}

// group-local arrive: 64 blocks -> 4 subgroups of 16 + master (per group)
__device__ __forceinline__ void bar_arrive_grp(int g, int bg) {
    __threadfence();                               // release prior global stores
    unsigned o = atomicAdd(&g_cnt1[g * 4 + (bg >> 4)].v, 1u);
    if (o == 15u) {
        unsigned o2 = atomicAdd(&g_cnt2g[g].v, 1u);
        if (o2 == 3u) {
            #pragma unroll
            for (int i = 0; i < 4; i++) atomicExch(&g_cnt1[g * 4 + i].v, 0u);
            atomicExch(&g_cnt2g[g].v, 0u);
            __threadfence();
            atomicAdd(&g_geng[g].v, 1u);
        }
    }
}

// ============================================================================
// P1: permute xs -> g_xsA_h (fp16 A-frag layout).  (round-12, proven)
// ============================================================================
__global__ void __launch_bounds__(256) permA_kernel(const float* __restrict__ xs) {
    size_t x = (size_t)blockIdx.x * 256 + threadIdx.x;   // < 4,194,304
    int lane  = (int)(x & 31);
    int ki    = (int)((x >> 5) & 63);
    int strip = (int)(x >> 11);
    int r  = strip * 16 + (lane >> 2);
    int k  = ki * 16 + (lane & 3) * 2;
    auto ld2 = [&](int m, int kk) -> unsigned {
        int b = m & 63, t = m >> 6;
        const float* p = xs + ((size_t)b * T_ + t) * D_ + kk;
        return pack_h2(p[0], p[1]);
    };
    uint4 v;
    v.x = ld2(r,     k);
    v.y = ld2(r + 8, k);
    v.z = ld2(r,     k + 8);
    v.w = ld2(r + 8, k + 8);
    reinterpret_cast<uint4*>(g_xsA_h)[x] = v;
}

// ============================================================================
// P2: permute Wx -> g_WxB_h (fp16 B-frag pair layout).  (round-12, proven)
// ============================================================================
__global__ void __launch_bounds__(256) permB_kernel(const float* __restrict__ Wx) {
    size_t y = (size_t)blockIdx.x * 256 + threadIdx.x;   // < 524,288
    int lane = (int)(y & 31);
    int ki   = (int)((y >> 5) & 63);
    int ng2  = (int)(y >> 11);
    int tk = (lane & 3) * 2;
    int n  = lane >> 2;
    int kb = ki * 16;
    unsigned wd[4];
    #pragma unroll
    for (int w = 0; w < 4; w++) {
        int ng   = ng2 * 2 + (w >> 1);
        int krow = kb + tk + 8 * (w & 1);
        const float* colp = Wx + (size_t)ng * 8 + n;
        wd[w] = pack_h2(__ldg(colp + (size_t)krow * G4_),
                        __ldg(colp + (size_t)(krow + 1) * G4_));
    }
    reinterpret_cast<uint4*>(g_WxB_h)[y] = make_uint4(wd[0], wd[1], wd[2], wd[3]);
}

// ============================================================================
// Kernel G: xproj = xsA_h @ WxB_h  (round-14 version, proven, byte-identical)
// BM=256, BN=128, 8 warps (wm 0..3 x wn 0..1), warp tile m64 x n64.
// ============================================================================
__global__ void __launch_bounds__(256) xproj_kernel() {
    extern __shared__ uint4 smG[];   // 3 stages x 3072 uint4 = 147,456 B
    const int tid  = threadIdx.x;
    const int lane = tid & 31;
    const int w    = tid >> 5;
    const int wm   = w >> 1;
    const int wn   = w & 1;
    const int mt   = blockIdx.y;
    const int nt   = blockIdx.x;

    const uint4* xsA = reinterpret_cast<const uint4*>(g_xsA_h);
    const uint4* WxB = reinterpret_cast<const uint4*>(g_WxB_h);

    auto issue = [&](int ch) {
        uint4* stA = smG + (ch % 3) * 3072;
        uint4* stB = stA + 2048;
        #pragma unroll
        for (int it = 0; it < 8; it++) {            // A: 2048 uint4
            int lin = tid + it * 256;
            int ln  = lin & 31;
            int dki = (lin >> 5) & 3;
            int st  = lin >> 7;
            cp_async16(&stA[(st * 4 + dki) * 32 + ln],
                       &xsA[((size_t)(mt * 16 + st) * 64 + ch * 4 + dki) * 32 + ln]);
        }
        #pragma unroll
        for (int it = 0; it < 4; it++) {            // B: 1024 uint4
            int lin = tid + it * 256;
            int ln  = lin & 31;
            int dki = (lin >> 5) & 3;
            int lg  = lin >> 7;
            cp_async16(&stB[(lg * 4 + dki) * 32 + ln],
                       &WxB[((size_t)(nt * 8 + lg) * 64 + ch * 4 + dki) * 32 + ln]);
        }
    };

    float4 acc[4][8];
    #pragma unroll
    for (int s = 0; s < 4; s++)
        #pragma unroll
        for (int o = 0; o < 8; o++)
            acc[s][o] = make_float4(0.f, 0.f, 0.f, 0.f);

    issue(0); cp_commit();
    issue(1); cp_commit();

    #pragma unroll 1
    for (int ch = 0; ch < 16; ch++) {
        __syncthreads();
        if (ch + 2 < 16) { issue(ch + 2); cp_commit(); }
        if (ch < 14) cp_wait<2>(); else if (ch == 14) cp_wait<1>(); else cp_wait<0>();
        __syncthreads();

        const uint4* stA = smG + (ch % 3) * 3072;
        const uint4* stB = stA + 2048;
        #pragma unroll
        for (int d = 0; d < 4; d++) {
            uint4 a[4];
            #pragma unroll
            for (int s = 0; s < 4; s++)
                a[s] = stA[((wm * 4 + s) * 4 + d) * 32 + lane];
            #pragma unroll
            for (int p = 0; p < 4; p++) {
                uint4 wv = stB[((wn * 4 + p) * 4 + d) * 32 + lane];
                #pragma unroll
                for (int s = 0; s < 4; s++) {
                    mma_f16(acc[s][2 * p],     a[s], wv.x, wv.y);
                    mma_f16(acc[s][2 * p + 1], a[s], wv.z, wv.w);
                }
            }
        }
    }

    int r  = lane >> 2;
    int c2 = (lane & 3) * 2;
    #pragma unroll
    for (int s = 0; s < 4; s++)
        #pragma unroll
        for (int o = 0; o < 8; o++) {
            size_t row = (size_t)mt * 256 + (wm * 4 + s) * 16 + r;
            size_t col = (size_t)nt * 128 + (wn * 8 + o) * 8 + c2;
            *reinterpret_cast<float2*>(g_xproj + row * G4_ + col) =
                make_float2(acc[s][o].x, acc[s][o].y);
            *reinterpret_cast<float2*>(g_xproj + (row + 8) * G4_ + col) =
                make_float2(acc[s][o].z, acc[s][o].w);
        }
}

// ============================================================================
// Kernel B: persistent LSTM scan, 128 blocks x 128 thr (4 warps), fp16,
//   TWO INDEPENDENT GROUPS over the batch (recurrence is per-row independent):
//   group g = bIdx>>6 owns batch rows [g*32,+32); block bg = bIdx&63 owns
//   h-cols [bg*16,+16) (= hperm ki == bg). Each group has its OWN barrier
//   (64 arrivals) and reads ONLY its group's h strips (2g, 2g+1): broadcast
//   = 64KB/block -> 8MB/step chip-wide (halved vs R12/R14).
//   Warp kq: local rows 0..31 (2 strips) x 64 gate-cols over k-quarter kq;
//   per ki: 2 A + 4 B LDS.128 -> 16 MMAs (R13-verified mapping). Warp-local
//   cp.async pipeline (no in-loop syncthreads, R12-verified). sg separate.
// ============================================================================
__global__ void __launch_bounds__(128, 1) lstm_scan_kernel(
    const float* __restrict__ c0, const float* __restrict__ h0,
    const float* __restrict__ Wh, const float* __restrict__ bias,
    float* __restrict__ out)
{
    extern __shared__ float sm[];
    uint4* Whs4 = reinterpret_cast<uint4*>(sm);            // 8192 uint4 = 128KB
    uint4* hs4  = reinterpret_cast<uint4*>(sm) + 8192;     // 2048 uint4 = 32KB
    float* sg   = sm + 32768 + 8192;                       // 8448 floats = 33KB

    const int tid  = threadIdx.x;
    const int lane = tid & 31;
    const int kq   = tid >> 5;           // warp id == k-quarter (256 k)
    const int bIdx = blockIdx.x;
    const int g    = bIdx >> 6;          // batch group 0..1
    const int bg   = bIdx & 63;          // block-in-group == owned hperm ki
    const int j0   = bg * 16;

    // ---- build Whs (fp16 B-frag pairs, 64 gate-cols; R13-verified formula):
    //   col c = (p*2 + (ww>>1))*8 + (lane>>2); gate = c>>4, hcol = c&15
    for (int i = tid; i < 8192; i += 128) {
        int ln  = i & 31;
        int p   = (i >> 5) & 3;
        int ki2 = (i >> 7) & 15;
        int kqq = i >> 11;
        int tk = (ln & 3) * 2;
        int nn = ln >> 2;
        int kb = kqq * 256 + ki2 * 16;
        unsigned wd[4];
        #pragma unroll
        for (int ww = 0; ww < 4; ww++) {
            int c    = (p * 2 + (ww >> 1)) * 8 + nn;   // 0..63
            int gate = c >> 4, hcol = c & 15;
            int krow = kb + tk + 8 * (ww & 1);
            const float* colp = Wh + (size_t)gate * H_ + j0 + hcol;
            wd[ww] = pack_h2(__ldg(colp + (size_t)krow * G4_),
                             __ldg(colp + (size_t)(krow + 1) * G4_));
        }
        Whs4[i] = make_uint4(wd[0], wd[1], wd[2], wd[3]);
    }

    // ---- per-thread ownership: col j = j0 + (tid&15); local rows rowb + 8q
    const int rowb = tid >> 4;           // 0..7
    const int jj   = tid & 15;
    const int j    = j0 + jj;
    int bq[4];                           // GLOBAL batch rows
    #pragma unroll
    for (int q = 0; q < 4; q++) bq[q] = g * 32 + rowb + 8 * q;

    float creg[4], bia[4];
    #pragma unroll
    for (int gg = 0; gg < 4; gg++) bia[gg] = __ldg(bias + gg * H_ + j);
    #pragma unroll
    for (int q = 0; q < 4; q++) creg[q] = __ldg(c0 + (size_t)bq[q] * H_ + j);

    // ---- h write coords (fp16 A-frag; ki == bg; strip = global row>>4)
    int strip_w[4], lane_w[4], v_w[4];
    const int hi_w = jj & 1;
    #pragma unroll
    for (int q = 0; q < 4; q++) {
        int lr  = rowb + 8 * q;          // local row 0..31
        int r16 = lr & 15;
        strip_w[q] = g * 2 + (lr >> 4);
        lane_w[q]  = (r16 & 7) * 4 + ((jj & 7) >> 1);
        v_w[q]     = ((jj >> 3) << 1) | (r16 >> 3);
    }

    // ---- init g_hperm_h[0] = fp16(h0)
    #pragma unroll
    for (int q = 0; q < 4; q++) {
        size_t hidx = ((((size_t)bg * 4 + strip_w[q]) * 32 + lane_w[q]) * 4 + v_w[q]) * 2 + hi_w;
        g_hperm_h[0][hidx] = __float2half_rn(__ldg(h0 + (size_t)bq[q] * H_ + j));
    }

    // ---- xproj prefetch
    float xpr[4][4];
    auto prefetch_xp = [&](int t) {
        const float* xp = g_xproj + (size_t)t * B_ * G4_;
        #pragma unroll
        for (int q = 0; q < 4; q++)
            #pragma unroll
            for (int gg = 0; gg < 4; gg++)
                xpr[q][gg] = __ldg(xp + (size_t)bq[q] * G4_ + gg * H_ + j);
    };
    prefetch_xp(0);

    // ---- initial group sync
    __syncthreads();
    {
        if (tid == 0) {
            volatile unsigned* genp = &g_geng[g].v;
            unsigned mygen = *genp;
            bar_arrive_grp(g, bg);
            while (*genp == mygen) { }
            __threadfence();
        }
        __syncthreads();
    }

    for (int t = 0; t < T_; t++) {
        const uint4* hc4 = reinterpret_cast<const uint4*>(g_hperm_h[t & 1]);
        __half* hnext    = g_hperm_h[(t + 1) & 1];

        // warp-local issue of chunk ci (2 ki x 2 group strips): 128 uint4
        auto issue = [&](int ci) {
            uint4* dst = hs4 + kq * 512 + (ci & 3) * 128;
            #pragma unroll
            for (int it = 0; it < 4; it++) {
                int dki = it >> 1;
                int sL  = it & 1;
                int ki  = kq * 16 + ci * 2 + dki;
                cp_async16(&dst[(dki * 2 + sL) * 32 + lane],
                           &hc4[((size_t)ki * 4 + (g * 2 + sL)) * 32 + lane]);
            }
        };

        issue(0); cp_commit();
        issue(1); cp_commit();
        issue(2); cp_commit();
        issue(3); cp_commit();

        float4 acc[2][8];   // [local strip][octet]
        #pragma unroll
        for (int s = 0; s < 2; s++)
            #pragma unroll
            for (int o = 0; o < 8; o++)
                acc[s][o] = make_float4(0.f, 0.f, 0.f, 0.f);

        #pragma unroll 4
        for (int ch = 0; ch < 8; ch++) {
            if (ch < 5)       cp_wait<3>();
            else if (ch == 5) cp_wait<2>();
            else if (ch == 6) cp_wait<1>();
            else              cp_wait<0>();

            const uint4* st = hs4 + kq * 512 + (ch & 3) * 128;
            #pragma unroll
            for (int d = 0; d < 2; d++) {
                int ki2 = ch * 2 + d;
                uint4 a0 = st[(d * 2 + 0) * 32 + lane];
                uint4 a1 = st[(d * 2 + 1) * 32 + lane];
                #pragma unroll
                for (int p = 0; p < 4; p++) {
                    uint4 wv = Whs4[((kq * 16 + ki2) * 4 + p) * 32 + lane];
                    mma_f16(acc[0][2 * p],     a0, wv.x, wv.y);
                    mma_f16(acc[0][2 * p + 1], a0, wv.z, wv.w);
                    mma_f16(acc[1][2 * p],     a1, wv.x, wv.y);
                    mma_f16(acc[1][2 * p + 1], a1, wv.z, wv.w);
                }
            }
            if (ch + 4 < 8) { issue(ch + 4); cp_commit(); }
        }

        // ---- stage partials: sg[kq][local row (stride 66)][col = o*8 + c2]
        {
            int r  = lane >> 2;
            int c2 = (lane & 3) * 2;
            float* base = sg + (size_t)kq * 32 * 66;
            #pragma unroll
            for (int s = 0; s < 2; s++)
                #pragma unroll
                for (int o = 0; o < 8; o++) {
                    int row0 = s * 16 + r;
                    *reinterpret_cast<float2*>(base + row0 * 66 + o * 8 + c2) =
                        make_float2(acc[s][o].x, acc[s][o].y);
                    *reinterpret_cast<float2*>(base + (row0 + 8) * 66 + o * 8 + c2) =
                        make_float2(acc[s][o].z, acc[s][o].w);
                }
        }
        __syncthreads();

        // ---- reduce 4 k-quarters + fused elementwise (flax order i,f,g,o)
        float hnv[4];
        #pragma unroll
        for (int q = 0; q < 4; q++) {
            int lr = rowb + 8 * q;
            float gv[4];
            #pragma unroll
            for (int gg = 0; gg < 4; gg++) {
                float sum = 0.f;
                #pragma unroll
                for (int kk = 0; kk < 4; kk++)
                    sum += sg[(size_t)kk * 32 * 66 + lr * 66 + gg * 16 + jj];
                gv[gg] = sum;
            }
            float pi = gv[0] + xpr[q][0] + bia[0];
            float pf = gv[1] + xpr[q][1] + bia[1];
            float pg = gv[2] + xpr[q][2] + bia[2];
            float po = gv[3] + xpr[q][3] + bia[3];
            float cn = sigmoid_f(pf) * creg[q] + sigmoid_f(pi) * tanh_f(pg);
            float hn = sigmoid_f(po) * tanh_f(cn);
            creg[q] = cn;
            hnv[q] = hn;
        }

        // ---- write hnext (fp16, permuted)
        #pragma unroll
        for (int q = 0; q < 4; q++) {
            size_t hidx = ((((size_t)bg * 4 + strip_w[q]) * 32 + lane_w[q]) * 4 + v_w[q]) * 2 + hi_w;
            hnext[hidx] = __float2half_rn(hnv[q]);
        }

        // ---- group barrier arrive (releases h stores)
        __syncthreads();
        unsigned mygen = 0;
        if (tid == 0) {
            volatile unsigned* genp = &g_geng[g].v;
            mygen = *genp;
            bar_arrive_grp(g, bg);
        }

        // ---- hidden work between arrive and wait: ys stores + next prefetch
        #pragma unroll
        for (int q = 0; q < 4; q++)
            out[2 * B_ * H_ + ((size_t)bq[q] * T_ + t) * H_ + j] = hnv[q];
        if (t == T_ - 1) {
            #pragma unroll
            for (int q = 0; q < 4; q++)
                out[B_ * H_ + (size_t)bq[q] * H_ + j] = hnv[q];
        }
        if (t + 1 < T_) prefetch_xp(t + 1);

        // ---- group barrier wait
        if (tid == 0) {
            volatile unsigned* genp = &g_geng[g].v;
            while (*genp == mygen) { }
            __threadfence();                    // acquire
        }
        __syncthreads();
    }

    // cT
    #pragma unroll
    for (int q = 0; q < 4; q++)
        out[(size_t)bq[q] * H_ + j] = creg[q];
}

// ============================================================================
// Launch. Inputs: c0, h0, xs, Wx, Wh, b. Output fp32: [cT][hT][ys]
// ============================================================================
extern "C" void kernel_launch(void* const* d_in, const int* in_sizes, int n_in,
                              void* d_out, int out_size) {
    const float* c0   = (const float*)d_in[0];
    const float* h0   = (const float*)d_in[1];
    const float* xs   = (const float*)d_in[2];
    const float* Wx   = (const float*)d_in[3];
    const float* Wh   = (const float*)d_in[4];
    const float* bias = (const float*)d_in[5];
    float* out = (float*)d_out;

    constexpr int G_SMEM    = 3 * 3072 * 16;                  // 147,456 B
    constexpr int SCAN_SMEM = (32768 + 8192 + 8448) * 4;      // 197,632 B
    cudaFuncSetAttribute(xproj_kernel,
                         cudaFuncAttributeMaxDynamicSharedMemorySize, G_SMEM);
    cudaFuncSetAttribute(lstm_scan_kernel,
                         cudaFuncAttributeMaxDynamicSharedMemorySize, SCAN_SMEM);

    permA_kernel<<<16384, 256>>>(xs);     // 4,194,304 uint4 / 256
    permB_kernel<<<2048, 256>>>(Wx);      // 524,288 uint4 / 256
    dim3 gridG(32, 128);                  // nt x mt (BM=256)
    xproj_kernel<<<gridG, 256, G_SMEM>>>();
    lstm_scan_kernel<<<128, 128, SCAN_SMEM>>>(c0, h0, Wh, bias, out);
}

// round 16
// speedup vs baseline: 1.3938x; 1.0999x over previous
#include <cuda_runtime.h>
#include <cuda_fp16.h>
#include <cstdint>
#include <math.h>

// Problem dims (SimpleLSTM): B=64, T=512, D=1024, H=1024
#define B_  64
#define T_  512
#define D_  1024
#define H_  1024
#define G4_ 4096   // 4*H

// ---------------- scratch (device globals: allocation-free) ----------------
__device__ float g_xproj[(size_t)T_ * B_ * G4_];      // [T*B][4H] fp32 (m = t*64+b)
// xs in fp16 A-frag (m16n8k16) layout: uint4 idx ((strip*64 + ki)*32 + lane)
__device__ __half g_xsA_h[(size_t)2048 * 64 * 32 * 8];   // 64MB
// Wx in fp16 B-frag pair layout: uint4 idx ((ng2*64 + ki)*32 + lane)
__device__ __half g_WxB_h[(size_t)256 * 64 * 32 * 8];    // 8MB
// hidden state fp16 A-frag: uint4 idx ((ki*4 + strip)*32 + lane). Double buf.
__device__ __half g_hperm_h[2][B_ * H_];

// barrier state
struct PadCnt { unsigned v; unsigned pad[31]; };   // 128B spacing
__device__ PadCnt g_cnt1[8];     // initial barrier: [g*4 + sub]
__device__ PadCnt g_cnt2g[2];
__device__ PadCnt g_geng[2];
// per-subgroup step counters: [g*4 + sb]
__device__ PadCnt g_scnt[8];
__device__ PadCnt g_sgen[8];

// ---------------- helpers ----------------
__device__ __forceinline__ void cp_async16(void* dst, const void* src) {
    uint32_t s = (uint32_t)__cvta_generic_to_shared(dst);
    asm volatile("cp.async.cg.shared.global [%0], [%1], 16;\n" :: "r"(s), "l"(src));
}
__device__ __forceinline__ void cp_commit() { asm volatile("cp.async.commit_group;\n"); }
template<int N>
__device__ __forceinline__ void cp_wait() { asm volatile("cp.async.wait_group %0;\n" :: "n"(N)); }

__device__ __forceinline__ void mma_f16(float4& d, const uint4& a,
                                        unsigned b0, unsigned b1) {
    asm volatile(
        "mma.sync.aligned.m16n8k16.row.col.f32.f16.f16.f32 "
        "{%0,%1,%2,%3}, {%4,%5,%6,%7}, {%8,%9}, {%0,%1,%2,%3};"
        : "+f"(d.x), "+f"(d.y), "+f"(d.z), "+f"(d.w)
        : "r"(a.x), "r"(a.y), "r"(a.z), "r"(a.w), "r"(b0), "r"(b1));
}
__device__ __forceinline__ float sigmoid_f(float x) {
    return __fdividef(1.0f, 1.0f + __expf(-x));
}
__device__ __forceinline__ float tanh_f(float x) {
    return __fdividef(2.0f, 1.0f + __expf(-2.0f * x)) - 1.0f;
}
__device__ __forceinline__ unsigned pack_h2(float lo, float hi) {
    __half2 h2 = __floats2half2_rn(lo, hi);
    return *reinterpret_cast<unsigned*>(&h2);
}

// group-local initial barrier (R15-proven)
__device__ __forceinline__ void bar_arrive_grp(int g, int bg) {
    __threadfence();
    unsigned o = atomicAdd(&g_cnt1[g * 4 + (bg >> 4)].v, 1u);
    if (o == 15u) {
        unsigned o2 = atomicAdd(&g_cnt2g[g].v, 1u);
        if (o2 == 3u) {
            #pragma unroll
            for (int i = 0; i < 4; i++) atomicExch(&g_cnt1[g * 4 + i].v, 0u);
            atomicExch(&g_cnt2g[g].v, 0u);
            __threadfence();
            atomicAdd(&g_geng[g].v, 1u);
        }
    }
}

// ============================================================================
// P1: permute xs -> g_xsA_h (fp16 A-frag layout).  (round-12, proven)
// ============================================================================
__global__ void __launch_bounds__(256) permA_kernel(const float* __restrict__ xs) {
    size_t x = (size_t)blockIdx.x * 256 + threadIdx.x;   // < 4,194,304
    int lane  = (int)(x & 31);
    int ki    = (int)((x >> 5) & 63);
    int strip = (int)(x >> 11);
    int r  = strip * 16 + (lane >> 2);
    int k  = ki * 16 + (lane & 3) * 2;
    auto ld2 = [&](int m, int kk) -> unsigned {
        int b = m & 63, t = m >> 6;
        const float* p = xs + ((size_t)b * T_ + t) * D_ + kk;
        return pack_h2(p[0], p[1]);
    };
    uint4 v;
    v.x = ld2(r,     k);
    v.y = ld2(r + 8, k);
    v.z = ld2(r,     k + 8);
    v.w = ld2(r + 8, k + 8);
    reinterpret_cast<uint4*>(g_xsA_h)[x] = v;
}

// ============================================================================
// P2: permute Wx -> g_WxB_h (fp16 B-frag pair layout).  (round-12, proven)
// ============================================================================
__global__ void __launch_bounds__(256) permB_kernel(const float* __restrict__ Wx) {
    size_t y = (size_t)blockIdx.x * 256 + threadIdx.x;   // < 524,288
    int lane = (int)(y & 31);
    int ki   = (int)((y >> 5) & 63);
    int ng2  = (int)(y >> 11);
    int tk = (lane & 3) * 2;
    int n  = lane >> 2;
    int kb = ki * 16;
    unsigned wd[4];
    #pragma unroll
    for (int w = 0; w < 4; w++) {
        int ng   = ng2 * 2 + (w >> 1);
        int krow = kb + tk + 8 * (w & 1);
        const float* colp = Wx + (size_t)ng * 8 + n;
        wd[w] = pack_h2(__ldg(colp + (size_t)krow * G4_),
                        __ldg(colp + (size_t)(krow + 1) * G4_));
    }
    reinterpret_cast<uint4*>(g_WxB_h)[y] = make_uint4(wd[0], wd[1], wd[2], wd[3]);
}

// ============================================================================
// Kernel G: xproj = xsA_h @ WxB_h  (round-14 version, proven, byte-identical)
// ============================================================================
__global__ void __launch_bounds__(256) xproj_kernel() {
    extern __shared__ uint4 smG[];   // 3 stages x 3072 uint4 = 147,456 B
    const int tid  = threadIdx.x;
    const int lane = tid & 31;
    const int w    = tid >> 5;
    const int wm   = w >> 1;
    const int wn   = w & 1;
    const int mt   = blockIdx.y;
    const int nt   = blockIdx.x;

    const uint4* xsA = reinterpret_cast<const uint4*>(g_xsA_h);
    const uint4* WxB = reinterpret_cast<const uint4*>(g_WxB_h);

    auto issue = [&](int ch) {
        uint4* stA = smG + (ch % 3) * 3072;
        uint4* stB = stA + 2048;
        #pragma unroll
        for (int it = 0; it < 8; it++) {
            int lin = tid + it * 256;
            int ln  = lin & 31;
            int dki = (lin >> 5) & 3;
            int st  = lin >> 7;
            cp_async16(&stA[(st * 4 + dki) * 32 + ln],
                       &xsA[((size_t)(mt * 16 + st) * 64 + ch * 4 + dki) * 32 + ln]);
        }
        #pragma unroll
        for (int it = 0; it < 4; it++) {
            int lin = tid + it * 256;
            int ln  = lin & 31;
            int dki = (lin >> 5) & 3;
            int lg  = lin >> 7;
            cp_async16(&stB[(lg * 4 + dki) * 32 + ln],
                       &WxB[((size_t)(nt * 8 + lg) * 64 + ch * 4 + dki) * 32 + ln]);
        }
    };

    float4 acc[4][8];
    #pragma unroll
    for (int s = 0; s < 4; s++)
        #pragma unroll
        for (int o = 0; o < 8; o++)
            acc[s][o] = make_float4(0.f, 0.f, 0.f, 0.f);

    issue(0); cp_commit();
    issue(1); cp_commit();

    #pragma unroll 1
    for (int ch = 0; ch < 16; ch++) {
        __syncthreads();
        if (ch + 2 < 16) { issue(ch + 2); cp_commit(); }
        if (ch < 14) cp_wait<2>(); else if (ch == 14) cp_wait<1>(); else cp_wait<0>();
        __syncthreads();

        const uint4* stA = smG + (ch % 3) * 3072;
        const uint4* stB = stA + 2048;
        #pragma unroll
        for (int d = 0; d < 4; d++) {
            uint4 a[4];
            #pragma unroll
            for (int s = 0; s < 4; s++)
                a[s] = stA[((wm * 4 + s) * 4 + d) * 32 + lane];
            #pragma unroll
            for (int p = 0; p < 4; p++) {
                uint4 wv = stB[((wn * 4 + p) * 4 + d) * 32 + lane];
                #pragma unroll
                for (int s = 0; s < 4; s++) {
                    mma_f16(acc[s][2 * p],     a[s], wv.x, wv.y);
                    mma_f16(acc[s][2 * p + 1], a[s], wv.z, wv.w);
                }
            }
        }
    }

    int r  = lane >> 2;
    int c2 = (lane & 3) * 2;
    #pragma unroll
    for (int s = 0; s < 4; s++)
        #pragma unroll
        for (int o = 0; o < 8; o++) {
            size_t row = (size_t)mt * 256 + (wm * 4 + s) * 16 + r;
            size_t col = (size_t)nt * 128 + (wn * 8 + o) * 8 + c2;
            *reinterpret_cast<float2*>(g_xproj + row * G4_ + col) =
                make_float2(acc[s][o].x, acc[s][o].y);
            *reinterpret_cast<float2*>(g_xproj + (row + 8) * G4_ + col) =
                make_float2(acc[s][o].z, acc[s][o].w);
        }
}

// ============================================================================
// Kernel B: persistent LSTM scan, 128 blocks x 128 thr (4 warps), fp16.
//   Two independent batch groups (R15). NEW: per-k-quarter producer gens —
//   warp kq waits only g_sgen[g*4+kq] >= t (its h-col producers, subgroup kq
//   = blocks [16kq,+16) of the group); a block arrives on its OWN subgroup's
//   counter right after writing its h slice. No end-of-step wait: straggler
//   blocks only gate the single warp that consumes their columns.
//   WAR-safe: block writes buf[(t+1)&1] only after all its warps saw
//   gen >= t, i.e. the whole group finished WRITING step t-1's output, which
//   is strictly after the whole group finished READING buf[(t-1)&1].
// ============================================================================
__global__ void __launch_bounds__(128, 1) lstm_scan_kernel(
    const float* __restrict__ c0, const float* __restrict__ h0,
    const float* __restrict__ Wh, const float* __restrict__ bias,
    float* __restrict__ out)
{
    extern __shared__ float sm[];
    uint4* Whs4 = reinterpret_cast<uint4*>(sm);            // 8192 uint4 = 128KB
    uint4* hs4  = reinterpret_cast<uint4*>(sm) + 8192;     // 2048 uint4 = 32KB
    float* sg   = sm + 32768 + 8192;                       // 8448 floats = 33KB

    const int tid  = threadIdx.x;
    const int lane = tid & 31;
    const int kq   = tid >> 5;           // warp id == k-quarter (256 k)
    const int bIdx = blockIdx.x;
    const int g    = bIdx >> 6;          // batch group 0..1
    const int bg   = bIdx & 63;          // block-in-group == owned hperm ki
    const int sb   = bg >> 4;            // own subgroup (producer of cols)
    const int j0   = bg * 16;

    // ---- build Whs (fp16 B-frag pairs, 64 gate-cols; R13/R15-verified)
    for (int i = tid; i < 8192; i += 128) {
        int ln  = i & 31;
        int p   = (i >> 5) & 3;
        int ki2 = (i >> 7) & 15;
        int kqq = i >> 11;
        int tk = (ln & 3) * 2;
        int nn = ln >> 2;
        int kb = kqq * 256 + ki2 * 16;
        unsigned wd[4];
        #pragma unroll
        for (int ww = 0; ww < 4; ww++) {
            int c    = (p * 2 + (ww >> 1)) * 8 + nn;   // 0..63
            int gate = c >> 4, hcol = c & 15;
            int krow = kb + tk + 8 * (ww & 1);
            const float* colp = Wh + (size_t)gate * H_ + j0 + hcol;
            wd[ww] = pack_h2(__ldg(colp + (size_t)krow * G4_),
                             __ldg(colp + (size_t)(krow + 1) * G4_));
        }
        Whs4[i] = make_uint4(wd[0], wd[1], wd[2], wd[3]);
    }

    // ---- per-thread ownership: col j = j0 + (tid&15); local rows rowb + 8q
    const int rowb = tid >> 4;           // 0..7
    const int jj   = tid & 15;
    const int j    = j0 + jj;
    int bq[4];                           // GLOBAL batch rows
    #pragma unroll
    for (int q = 0; q < 4; q++) bq[q] = g * 32 + rowb + 8 * q;

    float creg[4], bia[4];
    #pragma unroll
    for (int gg = 0; gg < 4; gg++) bia[gg] = __ldg(bias + gg * H_ + j);
    #pragma unroll
    for (int q = 0; q < 4; q++) creg[q] = __ldg(c0 + (size_t)bq[q] * H_ + j);

    // ---- h write coords (fp16 A-frag; ki == bg; strip = global row>>4)
    int strip_w[4], lane_w[4], v_w[4];
    const int hi_w = jj & 1;
    #pragma unroll
    for (int q = 0; q < 4; q++) {
        int lr  = rowb + 8 * q;          // local row 0..31
        int r16 = lr & 15;
        strip_w[q] = g * 2 + (lr >> 4);
        lane_w[q]  = (r16 & 7) * 4 + ((jj & 7) >> 1);
        v_w[q]     = ((jj >> 3) << 1) | (r16 >> 3);
    }

    // ---- init g_hperm_h[0] = fp16(h0)
    #pragma unroll
    for (int q = 0; q < 4; q++) {
        size_t hidx = ((((size_t)bg * 4 + strip_w[q]) * 32 + lane_w[q]) * 4 + v_w[q]) * 2 + hi_w;
        g_hperm_h[0][hidx] = __float2half_rn(__ldg(h0 + (size_t)bq[q] * H_ + j));
    }

    // ---- xproj prefetch
    float xpr[4][4];
    auto prefetch_xp = [&](int t) {
        const float* xp = g_xproj + (size_t)t * B_ * G4_;
        #pragma unroll
        for (int q = 0; q < 4; q++)
            #pragma unroll
            for (int gg = 0; gg < 4; gg++)
                xpr[q][gg] = __ldg(xp + (size_t)bq[q] * G4_ + gg * H_ + j);
    };
    prefetch_xp(0);

    // ---- reset per-subgroup step counters (before initial barrier)
    if (tid == 0 && (bg & 15) == 0) {
        atomicExch(&g_scnt[g * 4 + sb].v, 0u);
        atomicExch(&g_sgen[g * 4 + sb].v, 0u);
    }

    // ---- initial group sync (h0 + Whs + counter resets visible)
    __syncthreads();
    {
        if (tid == 0) {
            volatile unsigned* genp = &g_geng[g].v;
            unsigned mygen = *genp;
            bar_arrive_grp(g, bg);
            while (*genp == mygen) { }
            __threadfence();
        }
        __syncthreads();
    }

    volatile unsigned* my_gen = &g_sgen[g * 4 + kq].v;   // producers of my cols

    for (int t = 0; t < T_; t++) {
        const uint4* hc4 = reinterpret_cast<const uint4*>(g_hperm_h[t & 1]);
        __half* hnext    = g_hperm_h[(t + 1) & 1];

        // ---- per-warp wait: my k-quarter's producers finished step t-1 output
        while (*my_gen < (unsigned)t) { }
        __threadfence();                 // acquire their h stores

        // warp-local issue of chunk ci (2 ki x 2 group strips): 128 uint4
        auto issue = [&](int ci) {
            uint4* dst = hs4 + kq * 512 + (ci & 3) * 128;
            #pragma unroll
            for (int it = 0; it < 4; it++) {
                int dki = it >> 1;
                int sL  = it & 1;
                int ki  = kq * 16 + ci * 2 + dki;
                cp_async16(&dst[(dki * 2 + sL) * 32 + lane],
                           &hc4[((size_t)ki * 4 + (g * 2 + sL)) * 32 + lane]);
            }
        };

        issue(0); cp_commit();
        issue(1); cp_commit();
        issue(2); cp_commit();
        issue(3); cp_commit();

        float4 acc[2][8];   // [local strip][octet]
        #pragma unroll
        for (int s = 0; s < 2; s++)
            #pragma unroll
            for (int o = 0; o < 8; o++)
                acc[s][o] = make_float4(0.f, 0.f, 0.f, 0.f);

        #pragma unroll 4
        for (int ch = 0; ch < 8; ch++) {
            if (ch < 5)       cp_wait<3>();
            else if (ch == 5) cp_wait<2>();
            else if (ch == 6) cp_wait<1>();
            else              cp_wait<0>();

            const uint4* st = hs4 + kq * 512 + (ch & 3) * 128;
            #pragma unroll
            for (int d = 0; d < 2; d++) {
                int ki2 = ch * 2 + d;
                uint4 a0 = st[(d * 2 + 0) * 32 + lane];
                uint4 a1 = st[(d * 2 + 1) * 32 + lane];
                #pragma unroll
                for (int p = 0; p < 4; p++) {
                    uint4 wv = Whs4[((kq * 16 + ki2) * 4 + p) * 32 + lane];
                    mma_f16(acc[0][2 * p],     a0, wv.x, wv.y);
                    mma_f16(acc[0][2 * p + 1], a0, wv.z, wv.w);
                    mma_f16(acc[1][2 * p],     a1, wv.x, wv.y);
                    mma_f16(acc[1][2 * p + 1], a1, wv.z, wv.w);
                }
            }
            if (ch + 4 < 8) { issue(ch + 4); cp_commit(); }
        }

        // ---- stage partials: sg[kq][local row (stride 66)][col = o*8 + c2]
        {
            int r  = lane >> 2;
            int c2 = (lane & 3) * 2;
            float* base = sg + (size_t)kq * 32 * 66;
            #pragma unroll
            for (int s = 0; s < 2; s++)
                #pragma unroll
                for (int o = 0; o < 8; o++) {
                    int row0 = s * 16 + r;
                    *reinterpret_cast<float2*>(base + row0 * 66 + o * 8 + c2) =
                        make_float2(acc[s][o].x, acc[s][o].y);
                    *reinterpret_cast<float2*>(base + (row0 + 8) * 66 + o * 8 + c2) =
                        make_float2(acc[s][o].z, acc[s][o].w);
                }
        }
        __syncthreads();

        // ---- reduce 4 k-quarters + fused elementwise (flax order i,f,g,o)
        float hnv[4];
        #pragma unroll
        for (int q = 0; q < 4; q++) {
            int lr = rowb + 8 * q;
            float gv[4];
            #pragma unroll
            for (int gg = 0; gg < 4; gg++) {
                float sum = 0.f;
                #pragma unroll
                for (int kk = 0; kk < 4; kk++)
                    sum += sg[(size_t)kk * 32 * 66 + lr * 66 + gg * 16 + jj];
                gv[gg] = sum;
            }
            float pi = gv[0] + xpr[q][0] + bia[0];
            float pf = gv[1] + xpr[q][1] + bia[1];
            float pg = gv[2] + xpr[q][2] + bia[2];
            float po = gv[3] + xpr[q][3] + bia[3];
            float cn = sigmoid_f(pf) * creg[q] + sigmoid_f(pi) * tanh_f(pg);
            float hn = sigmoid_f(po) * tanh_f(cn);
            creg[q] = cn;
            hnv[q] = hn;
        }

        // ---- write hnext (fp16, permuted)
        #pragma unroll
        for (int q = 0; q < 4; q++) {
            size_t hidx = ((((size_t)bg * 4 + strip_w[q]) * 32 + lane_w[q]) * 4 + v_w[q]) * 2 + hi_w;
            hnext[hidx] = __float2half_rn(hnv[q]);
        }

        // ---- arrive on OWN subgroup counter (releases this block's h stores)
        __syncthreads();
        if (tid == 0) {
            __threadfence();
            unsigned o = atomicAdd(&g_scnt[g * 4 + sb].v, 1u);
            if (o == 15u) {
                atomicExch(&g_scnt[g * 4 + sb].v, 0u);
                atomicAdd(&g_sgen[g * 4 + sb].v, 1u);
            }
        }

        // ---- post-arrive work: ys stores, hT, next xproj prefetch
        #pragma unroll
        for (int q = 0; q < 4; q++)
            out[2 * B_ * H_ + ((size_t)bq[q] * T_ + t) * H_ + j] = hnv[q];
        if (t == T_ - 1) {
            #pragma unroll
            for (int q = 0; q < 4; q++)
                out[B_ * H_ + (size_t)bq[q] * H_ + j] = hnv[q];
        }
        if (t + 1 < T_) prefetch_xp(t + 1);
    }

    // cT
    #pragma unroll
    for (int q = 0; q < 4; q++)
        out[(size_t)bq[q] * H_ + j] = creg[q];
}

// ============================================================================
// Launch. Inputs: c0, h0, xs, Wx, Wh, b. Output fp32: [cT][hT][ys]
// ============================================================================
extern "C" void kernel_launch(void* const* d_in, const int* in_sizes, int n_in,
                              void* d_out, int out_size) {
    const float* c0   = (const float*)d_in[0];
    const float* h0   = (const float*)d_in[1];
    const float* xs   = (const float*)d_in[2];
    const float* Wx   = (const float*)d_in[3];
    const float* Wh   = (const float*)d_in[4];
    const float* bias = (const float*)d_in[5];
    float* out = (float*)d_out;

    constexpr int G_SMEM    = 3 * 3072 * 16;                  // 147,456 B
    constexpr int SCAN_SMEM = (32768 + 8192 + 8448) * 4;      // 197,632 B
    cudaFuncSetAttribute(xproj_kernel,
                         cudaFuncAttributeMaxDynamicSharedMemorySize, G_SMEM);
    cudaFuncSetAttribute(lstm_scan_kernel,
                         cudaFuncAttributeMaxDynamicSharedMemorySize, SCAN_SMEM);

    permA_kernel<<<16384, 256>>>(xs);     // 4,194,304 uint4 / 256
    permB_kernel<<<2048, 256>>>(Wx);      // 524,288 uint4 / 256
    dim3 gridG(32, 128);                  // nt x mt (BM=256)
    xproj_kernel<<<gridG, 256, G_SMEM>>>();
    lstm_scan_kernel<<<128, 128, SCAN_SMEM>>>(c0, h0, Wh, bias, out);
}